// round 4
// baseline (speedup 1.0000x reference)
#include <cuda_runtime.h>
#include <math.h>

#define BB 2
#define SS 2048
#define EE 512
#define NHH 8
#define DHH 64
#define BH (BB*NHH)

// Scratch (device globals: allocation-free)
__device__ float g_ig[BH*SS];
__device__ float g_fg[BH*SS];
__device__ float g_u [BH*SS];   // ig_j - cs_j
__device__ float g_M [BH*SS];   // prefix max of u
__device__ float g_m [BH*SS];   // cs_i + M_i  (= max_log_D row max)

// ---- packed f32x2 helpers (Blackwell; ptxas never emits these from C++) ----
__device__ __forceinline__ unsigned long long fma2(unsigned long long a,
                                                   unsigned long long b,
                                                   unsigned long long c) {
    unsigned long long d;
    asm("fma.rn.f32x2 %0, %1, %2, %3;" : "=l"(d) : "l"(a), "l"(b), "l"(c));
    return d;
}
__device__ __forceinline__ unsigned long long pack2(float a, float b) {
    unsigned long long r;
    asm("mov.b64 %0, {%1, %2};" : "=l"(r) : "f"(a), "f"(b));
    return r;
}
__device__ __forceinline__ float2 unpack2(unsigned long long v) {
    float2 r;
    asm("mov.b64 {%0, %1}, %2;" : "=f"(r.x), "=f"(r.y) : "l"(v));
    return r;
}

// ---------------------------------------------------------------------------
// Kernel 1: gate projections. ig/fg[b,n,s] = concat(q,k,v)[b,s,:] . W[n,:] + b
// grid = B*S/8 blocks, 512 threads (16 warps; warp w -> head (w&7), gate (w>>3))
// ---------------------------------------------------------------------------
__global__ void gates_kernel(const float* __restrict__ q,
                             const float* __restrict__ k,
                             const float* __restrict__ v,
                             const float* __restrict__ Wi,
                             const float* __restrict__ bi,
                             const float* __restrict__ Wf,
                             const float* __restrict__ bf) {
    __shared__ float gin[8 * 1536];   // 48 KB: 8 rows of gate_in
    const int tid = threadIdx.x;
    const int r0  = blockIdx.x * 8;   // global row index base in [0, B*S)

    const float4* q4 = (const float4*)q;
    const float4* k4 = (const float4*)k;
    const float4* v4 = (const float4*)v;
    float4* gin4 = (float4*)gin;
    for (int idx = tid; idx < 8 * 384; idx += 512) {
        int row = idx / 384;
        int c4  = idx - row * 384;           // 0..383 (1536 floats)
        int r   = r0 + row;
        float4 val;
        if (c4 < 128)       val = q4[r * 128 + c4];
        else if (c4 < 256)  val = k4[r * 128 + (c4 - 128)];
        else                val = v4[r * 128 + (c4 - 256)];
        gin4[row * 384 + c4] = val;
    }
    __syncthreads();

    const int wid  = tid >> 5;
    const int lane = tid & 31;
    const int n    = wid & 7;
    const int isF  = wid >> 3;
    const float* W = (isF ? Wf : Wi) + n * 1536;
    const float  bias = isF ? bf[n] : bi[n];

    float wreg[48];
    #pragma unroll
    for (int t = 0; t < 48; t++) wreg[t] = W[t * 32 + lane];

    for (int row = 0; row < 8; row++) {
        const float* g = gin + row * 1536;
        float a0 = 0.f, a1 = 0.f, a2 = 0.f, a3 = 0.f;
        #pragma unroll
        for (int t = 0; t < 12; t++) {
            a0 += g[(4*t+0) * 32 + lane] * wreg[4*t+0];
            a1 += g[(4*t+1) * 32 + lane] * wreg[4*t+1];
            a2 += g[(4*t+2) * 32 + lane] * wreg[4*t+2];
            a3 += g[(4*t+3) * 32 + lane] * wreg[4*t+3];
        }
        float acc = (a0 + a1) + (a2 + a3);
        #pragma unroll
        for (int o = 16; o > 0; o >>= 1) acc += __shfl_xor_sync(0xffffffffu, acc, o);
        if (lane == 0) {
            int r = r0 + row;
            int b = r / SS, s = r - b * SS;
            float* dst = isF ? g_fg : g_ig;
            dst[(b * NHH + n) * SS + s] = acc + bias;
        }
    }
}

// ---------------------------------------------------------------------------
// Kernel 2: per-(b,n) sequence scan.
//   cs = cumsum(log_sigmoid(fg));  u = ig - cs;  M = prefix_max(u);  m = cs + M
// grid = BH blocks, 256 threads, 8 elements/thread
// ---------------------------------------------------------------------------
__global__ void scan_kernel() {
    __shared__ float sh[256];
    const int bh   = blockIdx.x;
    const int tid  = threadIdx.x;
    const int base = bh * SS + tid * 8;

    float csl[8];
    float run = 0.f;
    #pragma unroll
    for (int t = 0; t < 8; t++) {
        float x  = g_fg[base + t];
        float ls = fminf(x, 0.f) - log1pf(expf(-fabsf(x)));  // log_sigmoid
        run += ls;
        csl[t] = run;                 // local inclusive cumsum
    }
    sh[tid] = run;
    __syncthreads();
    #pragma unroll
    for (int off = 1; off < 256; off <<= 1) {
        float vv = (tid >= off) ? sh[tid - off] : 0.f;
        __syncthreads();
        sh[tid] += vv;
        __syncthreads();
    }
    float offs = (tid > 0) ? sh[tid - 1] : 0.f;

    float u[8], pm[8];
    float runm = -INFINITY;
    #pragma unroll
    for (int t = 0; t < 8; t++) {
        float cs = offs + csl[t];
        csl[t] = cs;
        float ut = g_ig[base + t] - cs;
        u[t] = ut;
        runm = fmaxf(runm, ut);
        pm[t] = runm;
    }
    __syncthreads();
    sh[tid] = runm;
    __syncthreads();
    #pragma unroll
    for (int off = 1; off < 256; off <<= 1) {
        float vv = (tid >= off) ? sh[tid - off] : -INFINITY;
        __syncthreads();
        sh[tid] = fmaxf(sh[tid], vv);
        __syncthreads();
    }
    float moffs = (tid > 0) ? sh[tid - 1] : -INFINITY;
    #pragma unroll
    for (int t = 0; t < 8; t++) {
        float Mi = fmaxf(moffs, pm[t]);
        g_u[base + t] = u[t];
        g_M[base + t] = Mi;
        g_m[base + t] = csl[t] + Mi;
    }
}

// ---------------------------------------------------------------------------
// Kernel 3: causal decayed attention + normalizer + per-head LayerNorm.
// Thread-per-row (128 rows/block), K/V tiles of 64 staged in shared (pure
// broadcast reads). Inner math in packed f32x2 (2x fp32 rate on Blackwell).
// grid = (S/128, BH); big tiles launched first for load balance.
// ---------------------------------------------------------------------------
__global__ void __launch_bounds__(128)
attn_kernel(const float* __restrict__ q,
            const float* __restrict__ k,
            const float* __restrict__ v,
            float* __restrict__ out) {
    __shared__ float4 ksh[64 * 16];   // 16 KB
    __shared__ float4 vsh[64 * 16];   // 16 KB
    __shared__ float  ush[64];

    const int bh  = blockIdx.y;
    const int b   = bh >> 3;
    const int n   = bh & 7;
    const int ti  = (int)gridDim.x - 1 - (int)blockIdx.x;  // big tiles first
    const int tid = threadIdx.x;
    const int i   = ti * 128 + tid;          // this thread's query row

    // load q row into packed registers (32 x f32x2)
    unsigned long long qv2[32];
    const float4* qp = (const float4*)q + (b * SS + i) * 128 + n * 16;
    #pragma unroll
    for (int t = 0; t < 16; t++) {
        float4 val = qp[t];
        qv2[2*t]   = pack2(val.x, val.y);
        qv2[2*t+1] = pack2(val.z, val.w);
    }

    const float Mi = g_M[bh * SS + i];

    unsigned long long acc2[32];
    #pragma unroll
    for (int t = 0; t < 32; t++) acc2[t] = 0ull;
    float ssum = 0.f;

    const float4* k4 = (const float4*)k;
    const float4* v4 = (const float4*)v;
    const int nchunks = 2 * ti + 2;          // j up to ti*128+127

    for (int c = 0; c < nchunks; c++) {
        const int j0 = c * 64;
        __syncthreads();
        // stage K/V chunk (64 rows x 64 floats each)
        for (int l = tid; l < 1024; l += 128) {
            int row = l >> 4;
            int c4  = l & 15;
            int g   = (b * SS + j0 + row) * 128 + n * 16 + c4;
            ksh[l] = k4[g];
            vsh[l] = v4[g];
        }
        if (tid < 64) ush[tid] = g_u[bh * SS + j0 + tid];
        __syncthreads();

        const bool full = (j0 + 63 <= i);   // all 64 j's causal for this row

        #pragma unroll 2
        for (int jj = 0; jj < 64; jj++) {
            // qk dot (64 elems) in packed f32x2: 4 independent chains of 8
            unsigned long long d0 = 0ull, d1 = 0ull, d2 = 0ull, d3 = 0ull;
            const unsigned long long* kr =
                reinterpret_cast<const unsigned long long*>(&ksh[jj * 16]);
            #pragma unroll
            for (int t = 0; t < 8; t++) {
                d0 = fma2(qv2[4*t],   kr[4*t],   d0);
                d1 = fma2(qv2[4*t+1], kr[4*t+1], d1);
                d2 = fma2(qv2[4*t+2], kr[4*t+2], d2);
                d3 = fma2(qv2[4*t+3], kr[4*t+3], d3);
            }
            float2 s0 = unpack2(d0);
            float2 s1 = unpack2(d1);
            float2 s2 = unpack2(d2);
            float2 s3 = unpack2(d3);
            float qk = ((s0.x + s0.y) + (s1.x + s1.y))
                     + ((s2.x + s2.y) + (s3.x + s3.y));
            qk *= 0.125f;                                  // DH^-0.5
            float w  = __expf(ush[jj] - Mi);               // <= 1
            float Cv = (full || (j0 + jj <= i)) ? qk * w : 0.f;
            ssum += Cv;
            unsigned long long cv2 = pack2(Cv, Cv);
            const unsigned long long* vr =
                reinterpret_cast<const unsigned long long*>(&vsh[jj * 16]);
            #pragma unroll
            for (int t = 0; t < 32; t++)
                acc2[t] = fma2(cv2, vr[t], acc2[t]);
        }
    }

    // unpack accumulators
    float accf[64];
    #pragma unroll
    for (int t = 0; t < 32; t++) {
        float2 p = unpack2(acc2[t]);
        accf[2*t]   = p.x;
        accf[2*t+1] = p.y;
    }

    // normalizer: max(|sum C|, exp(-max_log_D)) + eps
    const float mi   = g_m[bh * SS + i];
    const float norm = fmaxf(fabsf(ssum), __expf(-mi)) + 1e-6f;
    const float inv  = 1.0f / norm;

    // h = acc * inv; LayerNorm over DH (eps = 1e-5, no affine)
    float sum = 0.f;
    #pragma unroll
    for (int t = 0; t < 64; t++) sum += accf[t];
    const float mu = sum * inv * (1.0f / 64.0f);

    float var = 0.f;
    #pragma unroll
    for (int t = 0; t < 64; t++) {
        float dx = accf[t] * inv - mu;
        var += dx * dx;
    }
    var *= (1.0f / 64.0f);
    const float sc = rsqrtf(var + 1e-5f);

    // raw reshape of (B,NH,S,DH): contiguous write at ((b*NH+n)*S+i)*DH
    float4* o4 = (float4*)out + (bh * SS + i) * 16;
    #pragma unroll
    for (int t = 0; t < 16; t++) {
        o4[t] = make_float4((accf[4*t]   * inv - mu) * sc,
                            (accf[4*t+1] * inv - mu) * sc,
                            (accf[4*t+2] * inv - mu) * sc,
                            (accf[4*t+3] * inv - mu) * sc);
    }
}

// ---------------------------------------------------------------------------
extern "C" void kernel_launch(void* const* d_in, const int* in_sizes, int n_in,
                              void* d_out, int out_size) {
    const float* q  = (const float*)d_in[0];
    const float* k  = (const float*)d_in[1];
    const float* v  = (const float*)d_in[2];
    const float* Wi = (const float*)d_in[3];
    const float* bi = (const float*)d_in[4];
    const float* Wf = (const float*)d_in[5];
    const float* bf = (const float*)d_in[6];
    float* out = (float*)d_out;

    gates_kernel<<<(BB * SS) / 8, 512>>>(q, k, v, Wi, bi, Wf, bf);
    scan_kernel<<<BH, 256>>>();
    attn_kernel<<<dim3(SS / 128, BH), 128>>>(q, k, v, out);
}

// round 6
// speedup vs baseline: 2.7073x; 2.7073x over previous
#include <cuda_runtime.h>
#include <math.h>
#include <stdint.h>

#define BB 2
#define SS 2048
#define EE 512
#define NHH 8
#define DHH 64
#define BH (BB*NHH)
#define NCHUNK (SS/64)    // 32 chunks of 64

typedef unsigned long long ull;

// Scratch (device globals: allocation-free)
__device__ float g_ig[BH*SS];
__device__ float g_fg[BH*SS];
__device__ float g_u [BH*SS];      // ig_j - cs_j
__device__ float g_M [BH*SS];      // prefix max of u
__device__ float g_m [BH*SS];      // cs_i + M_i (= max_log_D row max)
__device__ float g_w [BH*SS];      // exp(u_j - cmax_of_chunk)
__device__ float g_cmax[BH*NCHUNK];

// ---- packed f32x2 helpers (Blackwell) ----
__device__ __forceinline__ ull fma2(ull a, ull b, ull c) {
    ull d;
    asm("fma.rn.f32x2 %0, %1, %2, %3;" : "=l"(d) : "l"(a), "l"(b), "l"(c));
    return d;
}
__device__ __forceinline__ ull add2(ull a, ull b) {
    ull d;
    asm("add.rn.f32x2 %0, %1, %2;" : "=l"(d) : "l"(a), "l"(b));
    return d;
}
__device__ __forceinline__ ull pack2(float a, float b) {
    ull r;
    asm("mov.b64 %0, {%1, %2};" : "=l"(r) : "f"(a), "f"(b));
    return r;
}
__device__ __forceinline__ float2 unpack2(ull v) {
    float2 r;
    asm("mov.b64 {%0, %1}, %2;" : "=f"(r.x), "=f"(r.y) : "l"(v));
    return r;
}
__device__ __forceinline__ uint32_t s2u(const void* p) {
    uint32_t a;
    asm("{ .reg .u64 t; cvta.to.shared.u64 t, %1; cvt.u32.u64 %0, t; }"
        : "=r"(a) : "l"(p));
    return a;
}
__device__ __forceinline__ void cp16(uint32_t d, const void* s) {
    asm volatile("cp.async.cg.shared.global [%0], [%1], 16;" :: "r"(d), "l"(s));
}
#define CP_COMMIT() asm volatile("cp.async.commit_group;")
template<int N> __device__ __forceinline__ void cp_wait() {
    asm volatile("cp.async.wait_group %0;" :: "n"(N));
}

// ---------------------------------------------------------------------------
// Kernel 1: gate projections (f32x2 MAC pairs).
// grid = B*S/8 blocks, 512 threads (warp w -> head (w&7), gate (w>>3))
// ---------------------------------------------------------------------------
__global__ void gates_kernel(const float* __restrict__ q,
                             const float* __restrict__ k,
                             const float* __restrict__ v,
                             const float* __restrict__ Wi,
                             const float* __restrict__ bi,
                             const float* __restrict__ Wf,
                             const float* __restrict__ bf) {
    __shared__ float gin[8 * 1536];   // 48 KB (static, at the limit)
    const int tid = threadIdx.x;
    const int r0  = blockIdx.x * 8;

    const float4* q4 = (const float4*)q;
    const float4* k4 = (const float4*)k;
    const float4* v4 = (const float4*)v;
    float4* gin4 = (float4*)gin;
    for (int idx = tid; idx < 8 * 384; idx += 512) {
        int row = idx / 384;
        int c4  = idx - row * 384;
        int r   = r0 + row;
        float4 val;
        if (c4 < 128)       val = q4[r * 128 + c4];
        else if (c4 < 256)  val = k4[r * 128 + (c4 - 128)];
        else                val = v4[r * 128 + (c4 - 256)];
        gin4[row * 384 + c4] = val;
    }
    __syncthreads();

    const int wid  = tid >> 5;
    const int lane = tid & 31;
    const int n    = wid & 7;
    const int isF  = wid >> 3;
    const ull* W2  = (const ull*)((isF ? Wf : Wi) + n * 1536);
    const float bias = isF ? bf[n] : bi[n];

    ull w2[24];
    #pragma unroll
    for (int t = 0; t < 24; t++) w2[t] = W2[t * 32 + lane];

    for (int row = 0; row < 8; row++) {
        const ull* g2 = (const ull*)(gin + row * 1536);
        ull a0 = 0ull, a1 = 0ull;
        #pragma unroll
        for (int t = 0; t < 12; t++) {
            a0 = fma2(g2[(2*t)   * 32 + lane], w2[2*t],   a0);
            a1 = fma2(g2[(2*t+1) * 32 + lane], w2[2*t+1], a1);
        }
        float2 s = unpack2(add2(a0, a1));
        float acc = s.x + s.y;
        #pragma unroll
        for (int o = 16; o > 0; o >>= 1) acc += __shfl_xor_sync(0xffffffffu, acc, o);
        if (lane == 0) {
            int r = r0 + row;
            int b = r / SS, sIdx = r - b * SS;
            float* dst = isF ? g_fg : g_ig;
            dst[(b * NHH + n) * SS + sIdx] = acc + bias;
        }
    }
}

// ---------------------------------------------------------------------------
// Kernel 2: per-(b,n) scan. cs=cumsum(logsig(fg)); u=ig-cs; M=prefmax(u);
// m=cs+M; plus per-64-chunk max (g_cmax) and g_w = exp(u - cmax).
// grid = BH blocks, 256 threads, 8 elems/thread (chunk = 8 threads).
// ---------------------------------------------------------------------------
__global__ void scan_kernel() {
    __shared__ float sh[256];
    const int bh   = blockIdx.x;
    const int tid  = threadIdx.x;
    const int base = bh * SS + tid * 8;

    float csl[8];
    float run = 0.f;
    #pragma unroll
    for (int t = 0; t < 8; t++) {
        float x  = g_fg[base + t];
        float ls = fminf(x, 0.f) - log1pf(expf(-fabsf(x)));  // log_sigmoid
        run += ls;
        csl[t] = run;
    }
    sh[tid] = run;
    __syncthreads();
    #pragma unroll
    for (int off = 1; off < 256; off <<= 1) {
        float vv = (tid >= off) ? sh[tid - off] : 0.f;
        __syncthreads();
        sh[tid] += vv;
        __syncthreads();
    }
    float offs = (tid > 0) ? sh[tid - 1] : 0.f;

    float u[8], pm[8];
    float runm = -INFINITY;
    #pragma unroll
    for (int t = 0; t < 8; t++) {
        float cs = offs + csl[t];
        csl[t] = cs;
        float ut = g_ig[base + t] - cs;
        u[t] = ut;
        runm = fmaxf(runm, ut);
        pm[t] = runm;
    }
    // chunk max over group of 8 threads (aligned within warp)
    float cm = runm;
    cm = fmaxf(cm, __shfl_xor_sync(0xffffffffu, cm, 1));
    cm = fmaxf(cm, __shfl_xor_sync(0xffffffffu, cm, 2));
    cm = fmaxf(cm, __shfl_xor_sync(0xffffffffu, cm, 4));
    if ((tid & 7) == 0) g_cmax[bh * NCHUNK + (tid >> 3)] = cm;

    __syncthreads();
    sh[tid] = runm;
    __syncthreads();
    #pragma unroll
    for (int off = 1; off < 256; off <<= 1) {
        float vv = (tid >= off) ? sh[tid - off] : -INFINITY;
        __syncthreads();
        sh[tid] = fmaxf(sh[tid], vv);
        __syncthreads();
    }
    float moffs = (tid > 0) ? sh[tid - 1] : -INFINITY;
    #pragma unroll
    for (int t = 0; t < 8; t++) {
        float Mi = fmaxf(moffs, pm[t]);
        g_u[base + t] = u[t];
        g_M[base + t] = Mi;
        g_m[base + t] = csl[t] + Mi;
        g_w[base + t] = __expf(u[t] - cm);
    }
}

// ---------------------------------------------------------------------------
// Kernel 3: causal decayed attention. Thread-per-row (128 rows/block),
// double-buffered cp.async K/V staging (DYNAMIC shared: 66560 B), exp hoisted
// out of the inner loop, decay-window truncation. grid = (S/128, BH).
//
// Dynamic smem layout (floats):
//   [0,      8192)  ksh : 2 bufs x 64 rows x 64
//   [8192,  16384)  vsh : 2 bufs x 64 rows x 64
//   [16384, 16512)  wsh : 2 bufs x 64
//   [16512, 16640)  ush : 2 bufs x 64
// ---------------------------------------------------------------------------
#define ATTN_SMEM_BYTES (16640 * 4)

__global__ void __launch_bounds__(128)
attn_kernel(const float* __restrict__ q,
            const float* __restrict__ k,
            const float* __restrict__ v,
            float* __restrict__ out) {
    extern __shared__ float dynsh[];
    float* ksh  = dynsh;              // [2][4096]
    float* vsh  = dynsh + 8192;       // [2][4096]
    float* wshp = dynsh + 16384;      // [2][64]
    float* ushp = dynsh + 16512;      // [2][64]

    const int bh  = blockIdx.y;
    const int b   = bh >> 3;
    const int n   = bh & 7;
    const int ti  = (int)gridDim.x - 1 - (int)blockIdx.x;  // big tiles first
    const int tid = threadIdx.x;
    const int i   = ti * 128 + tid;

    const uint32_t kb = s2u(ksh);            // byte addresses
    const uint32_t vb = kb + 32768u;
    const uint32_t wb = kb + 65536u;
    const uint32_t ub = kb + 66048u;

    // q row in packed registers
    ull qv2[32];
    const float4* qp = (const float4*)q + (b * SS + i) * 128 + n * 16;
    #pragma unroll
    for (int t = 0; t < 16; t++) {
        float4 val = qp[t];
        qv2[2*t]   = pack2(val.x, val.y);
        qv2[2*t+1] = pack2(val.z, val.w);
    }

    const float Mi = g_M[bh * SS + i];
    const int cdiag = i >> 6;                  // this thread's diagonal chunk
    const int c_end = 2 * ti + 2;

    // uniform truncation start: drop chunks dead for the whole block
    // (M is prefix-monotone, so row ti*128 has the block-min M)
    const float thr = g_M[bh * SS + ti * 128] - 88.0f;
    int c_start = 0;
    while (c_start < 2 * ti && g_cmax[bh * NCHUNK + c_start] <= thr) c_start++;

#define STAGE(cc, bufidx) do {                                               \
    int j0_ = (cc) * 64;                                                     \
    const float* kp_ = k + (size_t)(b * SS + j0_) * EE + n * 64;             \
    const float* vp_ = v + (size_t)(b * SS + j0_) * EE + n * 64;             \
    _Pragma("unroll")                                                        \
    for (int r_ = 0; r_ < 8; r_++) {                                         \
        int l_ = tid + 128 * r_; int row_ = l_ >> 4, c4_ = l_ & 15;          \
        cp16(kb + (bufidx) * 16384u + (uint32_t)l_ * 16u, kp_ + row_ * EE + c4_ * 4); \
        cp16(vb + (bufidx) * 16384u + (uint32_t)l_ * 16u, vp_ + row_ * EE + c4_ * 4); \
    }                                                                        \
    if (tid < 16)                                                            \
        cp16(wb + (bufidx) * 256u + (uint32_t)tid * 16u, g_w + bh * SS + j0_ + tid * 4); \
    else if (tid < 32)                                                       \
        cp16(ub + (bufidx) * 256u + (uint32_t)(tid - 16) * 16u, g_u + bh * SS + j0_ + (tid - 16) * 4); \
} while (0)

    ull acc2[32];
    #pragma unroll
    for (int t = 0; t < 32; t++) acc2[t] = 0ull;
    float ssum = 0.f;

    STAGE(c_start, 0);
    CP_COMMIT();

    for (int c = c_start; c < c_end; c++) {
        const int cur = (c - c_start) & 1;
        __syncthreads();                       // prior buf consumers done
        if (c + 1 < c_end) STAGE(c + 1, cur ^ 1);
        CP_COMMIT();
        cp_wait<1>();                          // chunk c landed
        __syncthreads();

        if (c < cdiag) {
            const float es = __expf(g_cmax[bh * NCHUNK + c] - Mi);  // <= 1
            if (es > 0.f) {
                const float qs = 0.125f * es;
                #pragma unroll 2
                for (int jj = 0; jj < 64; jj++) {
                    const ull* kr = (const ull*)(ksh + cur * 4096 + jj * 64);
                    ull d0 = 0ull, d1 = 0ull, d2 = 0ull, d3 = 0ull;
                    #pragma unroll
                    for (int t = 0; t < 8; t++) {
                        d0 = fma2(qv2[4*t],   kr[4*t],   d0);
                        d1 = fma2(qv2[4*t+1], kr[4*t+1], d1);
                        d2 = fma2(qv2[4*t+2], kr[4*t+2], d2);
                        d3 = fma2(qv2[4*t+3], kr[4*t+3], d3);
                    }
                    float2 s = unpack2(add2(add2(d0, d1), add2(d2, d3)));
                    float Cv = ((s.x + s.y) * qs) * wshp[cur * 64 + jj];
                    ssum += Cv;
                    ull cv2 = pack2(Cv, Cv);
                    const ull* vr = (const ull*)(vsh + cur * 4096 + jj * 64);
                    #pragma unroll
                    for (int t = 0; t < 32; t++)
                        acc2[t] = fma2(cv2, vr[t], acc2[t]);
                }
            }
        } else if (c == cdiag) {
            const int j0 = c * 64;
            #pragma unroll 2
            for (int jj = 0; jj < 64; jj++) {
                const ull* kr = (const ull*)(ksh + cur * 4096 + jj * 64);
                ull d0 = 0ull, d1 = 0ull, d2 = 0ull, d3 = 0ull;
                #pragma unroll
                for (int t = 0; t < 8; t++) {
                    d0 = fma2(qv2[4*t],   kr[4*t],   d0);
                    d1 = fma2(qv2[4*t+1], kr[4*t+1], d1);
                    d2 = fma2(qv2[4*t+2], kr[4*t+2], d2);
                    d3 = fma2(qv2[4*t+3], kr[4*t+3], d3);
                }
                float2 s = unpack2(add2(add2(d0, d1), add2(d2, d3)));
                float qk = (s.x + s.y) * 0.125f;
                float wq = __expf(ushp[cur * 64 + jj] - Mi);
                float Cv = (j0 + jj <= i) ? qk * wq : 0.f;
                ssum += Cv;
                ull cv2 = pack2(Cv, Cv);
                const ull* vr = (const ull*)(vsh + cur * 4096 + jj * 64);
                #pragma unroll
                for (int t = 0; t < 32; t++)
                    acc2[t] = fma2(cv2, vr[t], acc2[t]);
            }
        }
    }
#undef STAGE

    // unpack accumulators
    float accf[64];
    #pragma unroll
    for (int t = 0; t < 32; t++) {
        float2 p = unpack2(acc2[t]);
        accf[2*t]   = p.x;
        accf[2*t+1] = p.y;
    }

    // normalizer: max(|sum C|, exp(-max_log_D)) + eps
    const float mi   = g_m[bh * SS + i];
    const float norm = fmaxf(fabsf(ssum), __expf(-mi)) + 1e-6f;
    const float inv  = 1.0f / norm;

    // LayerNorm over DH (eps = 1e-5, no affine), applied after normalizer
    float sum = 0.f;
    #pragma unroll
    for (int t = 0; t < 64; t++) sum += accf[t];
    const float mu = sum * inv * (1.0f / 64.0f);

    float var = 0.f;
    #pragma unroll
    for (int t = 0; t < 64; t++) {
        float dx = accf[t] * inv - mu;
        var += dx * dx;
    }
    var *= (1.0f / 64.0f);
    const float sc = rsqrtf(var + 1e-5f);

    float4* o4 = (float4*)out + (bh * SS + i) * 16;
    #pragma unroll
    for (int t = 0; t < 16; t++) {
        o4[t] = make_float4((accf[4*t]   * inv - mu) * sc,
                            (accf[4*t+1] * inv - mu) * sc,
                            (accf[4*t+2] * inv - mu) * sc,
                            (accf[4*t+3] * inv - mu) * sc);
    }
}

// ---------------------------------------------------------------------------
extern "C" void kernel_launch(void* const* d_in, const int* in_sizes, int n_in,
                              void* d_out, int out_size) {
    const float* q  = (const float*)d_in[0];
    const float* k  = (const float*)d_in[1];
    const float* v  = (const float*)d_in[2];
    const float* Wi = (const float*)d_in[3];
    const float* bi = (const float*)d_in[4];
    const float* Wf = (const float*)d_in[5];
    const float* bf = (const float*)d_in[6];
    float* out = (float*)d_out;

    // opt-in to >48KB dynamic smem (idempotent, capture-safe host call)
    cudaFuncSetAttribute(attn_kernel,
                         cudaFuncAttributeMaxDynamicSharedMemorySize,
                         ATTN_SMEM_BYTES);

    gates_kernel<<<(BB * SS) / 8, 512>>>(q, k, v, Wi, bi, Wf, bf);
    scan_kernel<<<BH, 256>>>();
    attn_kernel<<<dim3(SS / 128, BH), 128, ATTN_SMEM_BYTES>>>(q, k, v, out);
}